// round 15
// baseline (speedup 1.0000x reference)
#include <cuda_runtime.h>
#include <cuda_fp16.h>

typedef unsigned long long u64;
typedef unsigned int u32;

#define BD   32
#define LD   513
#define DD   8
#define HD   64
#define WINW 16
#define NW   32
#define OUTD 4
#define NPAIR 28
#define NTH  512

// ---- smem layout (float offsets; 16B-aligned). W3 half in regs (32/thread). ----
#define OFF_W1H  0        // uint4[8*128] : W1H[c*128+r], K=64
#define OFF_W2H  4096     // uint4[16*128]: W2H[c*128+k], K=128
#define OFF_G    12288    // 1152
#define OFF_Y    13440    // 64
#define OFF_YMID 13504    // 64
#define OFF_K1   13568    // 64
#define OFF_CM   13632    // 64
#define OFF_S1   13696    // 128
#define OFF_S2   13824    // 128
#define OFF_F    13952    // 512 (full sf; halves exchanged via DSMEM)
#define OFF_SP   14464    // 1024 = 2 slots x 512 (double-buffered by Heun phase)
#define OFF_YB   15488    // 32 u32
#define OFF_YMB  15520    // 32 u32
#define OFF_H1B  15552    // 64 u32
#define OFF_H2B  15616    // 64 u32
#define OFF_VPB  15680    // 128 u32 (4 local j x 32)
#define OFF_D1B  15808    // 256 u32 (4 local j x 64)
#define OFF_EFB  16064    // 256 u32 (4 local j x 64)
#define OFF_B1   16320    // 128
#define OFF_B2   16448    // 128
#define OFF_B3   16576    // 512
#define OFF_WR   17088    // 256
#define OFF_BR   17344    // 4
#define OFF_SHIFT 17348
#define OFF_MB   17352    // 2 x u64 mbarriers (mb_sf, mb_sp)
#define OFF_PART 17356    // 4096 staging (init only)
#define SMEM_FLOATS 21452 // 85,808 B

__device__ const signed char PI_[NPAIR] = {0,0,0,0,0,0,0, 1,1,1,1,1,1, 2,2,2,2,2, 3,3,3,3, 4,4,4, 5,5, 6};
__device__ const signed char PJ_[NPAIR] = {1,2,3,4,5,6,7, 2,3,4,5,6,7, 3,4,5,6,7, 4,5,6,7, 5,6,7, 6,7, 7};

// ---------- fast math ----------
__device__ __forceinline__ float ex2f(float x){ float y; asm("ex2.approx.f32 %0, %1;" : "=f"(y) : "f"(x)); return y; }
__device__ __forceinline__ float rcpf(float x){ float y; asm("rcp.approx.f32 %0, %1;" : "=f"(y) : "f"(x)); return y; }
__device__ __forceinline__ float sigf(float x){ return rcpf(1.0f + ex2f(-1.4426950408889634f * x)); }
__device__ __forceinline__ float tanh_fast(float x){
    float t = ex2f(2.8853900817779268f * x);
    return 1.0f - 2.0f * rcpf(t + 1.0f);
}
__device__ __forceinline__ float lipswish(float x, float* dout){
    float s = sigf(x);
    *dout = 0.909f * s * fmaf(x, 1.0f - s, 1.0f);
    return 0.909f * x * s;
}

// ---------- fp16 helpers ----------
__device__ __forceinline__ __half2 u2h(u32 u){ return *reinterpret_cast<__half2*>(&u); }
__device__ __forceinline__ u32 h2u(__half2 h){ return *reinterpret_cast<u32*>(&h); }
__device__ __forceinline__ u32 pkh(float lo, float hi){ return h2u(__floats2half2_rn(lo, hi)); }
__device__ __forceinline__ float hsum2h(__half2 a, __half2 b){
    float2 fa = __half22float2(a), fb = __half22float2(b);
    return (fa.x + fa.y) + (fb.x + fb.y);
}
__device__ __forceinline__ void q_fma(__half2& a0, __half2& a1, uint4 w, uint4 x){
    a0 = __hfma2(u2h(w.x), u2h(x.x), a0);
    a1 = __hfma2(u2h(w.y), u2h(x.y), a1);
    a0 = __hfma2(u2h(w.z), u2h(x.z), a0);
    a1 = __hfma2(u2h(w.w), u2h(x.w), a1);
}

__device__ __forceinline__ int pidx(int i, int j) { return (i * (13 - i)) / 2 + j - 1; }

// ---------- cluster helpers ----------
__device__ __forceinline__ u32 my_cluster_rank(){
    u32 r; asm("mov.u32 %0, %%cluster_ctarank;" : "=r"(r)); return r;
}
__device__ __forceinline__ void st_peer_f32(u32 laddr, u32 peer, float v){
    u32 raddr;
    asm volatile("mapa.shared::cluster.u32 %0, %1, %2;" : "=r"(raddr) : "r"(laddr), "r"(peer));
    asm volatile("st.shared::cluster.f32 [%0], %1;" :: "r"(raddr), "f"(v) : "memory");
}
__device__ __forceinline__ void mbar_arrive_local(u32 mb){
    asm volatile("mbarrier.arrive.release.cluster.shared::cta.b64 _, [%0];" :: "r"(mb) : "memory");
}
__device__ __forceinline__ void mbar_arrive_peer(u32 mb, u32 peer){
    u32 ra;
    asm volatile("mapa.shared::cluster.u32 %0, %1, %2;" : "=r"(ra) : "r"(mb), "r"(peer));
    asm volatile("mbarrier.arrive.release.cluster.shared::cluster.b64 _, [%0];" :: "r"(ra) : "memory");
}
__device__ __forceinline__ void mbar_wait(u32 mb, u32 parity){
    u32 done;
    asm volatile(
        "{\n\t.reg .pred p;\n\t"
        "mbarrier.try_wait.parity.acquire.cluster.shared::cta.b64 p, [%1], %2;\n\t"
        "selp.b32 %0, 1, 0, p;\n\t}"
        : "=r"(done) : "r"(mb), "r"(parity) : "memory");
    while (!done){
        asm volatile(
            "{\n\t.reg .pred p;\n\t"
            "mbarrier.try_wait.parity.acquire.cluster.shared::cta.b64 p, [%1], %2, 0x989680;\n\t"
            "selp.b32 %0, 1, 0, p;\n\t}"
            : "=r"(done) : "r"(mb), "r"(parity) : "memory");
    }
}
#define CLUSTER_SYNC() do { \
    asm volatile("barrier.cluster.arrive.aligned;" ::: "memory"); \
    asm volatile("barrier.cluster.wait.aligned;" ::: "memory"); \
} while(0)

extern __shared__ float sm[];

#define ZH2 (__half2(__float2half_rn(0.f), __float2half_rn(0.f)))

// PH=1: acts=yb, writes sk1/symid(+pack). PH=2: acts=ymb, updates sy(+pack).
// Rank q owns rows qbase..qbase+255 (P3/P7) and j = jbase..jbase+3 (P4/P5/P6).
template<int PH>
__device__ __forceinline__ void vf_apply(int tid, const uint4* __restrict__ w3r,
                                         u32 peer, int qbase, int jbase, u32 smu,
                                         u32 mb_sf, u32 mb_sp, u32& par_sf, u32& par_sp,
                                         const float* __restrict__ gvec, float dt)
{
    const uint4* W1H = (const uint4*)(sm + OFF_W1H);
    const uint4* W2H = (const uint4*)(sm + OFF_W2H);
    float* ss1 = sm + OFF_S1;  float* ss2 = sm + OFF_S2;
    float* sf  = sm + OFF_F;
    float* sp  = sm + OFF_SP + (PH - 1) * 512;   // double-buffered by phase
    const u32 sp_u32 = smu + (OFF_SP + (PH - 1) * 512) * 4;
    const u32 sf_u32 = smu + OFF_F * 4;
    u32* H1B = (u32*)(sm + OFF_H1B);
    u32* H2B = (u32*)(sm + OFF_H2B);
    u32* VPB = (u32*)(sm + OFF_VPB);
    u32* D1B = (u32*)(sm + OFF_D1B);
    u32* EFB = (u32*)(sm + OFF_EFB);
    const float* scm = sm + OFF_CM;
    const int grp = tid >> 7;   // 4-warp group id (named barriers 2..5)

    // ---- P1 + P2 (tid<128; duplicated in both CTAs; named barrier between) ----
    if (tid < 128) {
        {   // P1: L1 forward
            const int r = tid;
            const uint4* A = (const uint4*)(sm + (PH == 1 ? OFF_YB : OFF_YMB));
            __half2 a0 = ZH2, a1 = ZH2, a2 = ZH2, a3 = ZH2;
            #pragma unroll
            for (int c = 0; c < 8; c += 2){
                q_fma(a0, a1, W1H[c * 128 + r], A[c]);
                q_fma(a2, a3, W1H[(c + 1) * 128 + r], A[c + 1]);
            }
            float pre = sm[OFF_B1 + r] + hsum2h(a0, a1) + hsum2h(a2, a3);
            float d; float hv = lipswish(pre, &d); ss1[r] = d;
            float part = __shfl_xor_sync(0xffffffffu, hv, 16);
            if (!(r & 16)) H1B[((r >> 5) << 4) | (r & 15)] = pkh(hv, part);
        }
        asm volatile("bar.sync 1, 128;" ::: "memory");
        {   // P2: L2 forward
            const int k = tid;
            const uint4* A = (const uint4*)H1B;
            __half2 a0 = ZH2, a1 = ZH2, a2 = ZH2, a3 = ZH2;
            #pragma unroll 4
            for (int c = 0; c < 16; c += 2){
                q_fma(a0, a1, W2H[c * 128 + k], A[c]);
                q_fma(a2, a3, W2H[(c + 1) * 128 + k], A[c + 1]);
            }
            float pre = sm[OFF_B2 + k] + hsum2h(a0, a1) + hsum2h(a2, a3);
            float d; float hv = lipswish(pre, &d); ss2[k] = d;
            float part = __shfl_xor_sync(0xffffffffu, hv, 16);
            if (!(k & 16)) H2B[((k >> 5) << 4) | (k & 15)] = pkh(hv, part);
        }
    }
    __syncthreads();

    // ---- P3: L3 forward, own 256 rows, 2 threads/row (K halves) ----
    {
        const int rowl = tid >> 1, kh = tid & 1, row = qbase + rowl;
        const uint4* A = (const uint4*)H2B + kh * 8;
        __half2 a0 = ZH2, a1 = ZH2, a2 = ZH2, a3 = ZH2;
        #pragma unroll
        for (int i = 0; i < 8; i += 2){
            q_fma(a0, a1, w3r[i], A[i]);
            q_fma(a2, a3, w3r[i + 1], A[i + 1]);
        }
        float part = hsum2h(a0, a1) + hsum2h(a2, a3);
        float other = __shfl_xor_sync(0xffffffffu, part, 1);
        if (!kh){
            float f = tanh_fast(sm[OFF_B3 + row] + part + other);
            sf[row] = f;
            st_peer_f32(sf_u32 + row * 4, peer, f);
        }
    }
    __syncwarp();
    if ((tid & 31) == 0){ mbar_arrive_local(mb_sf); mbar_arrive_peer(mb_sf, peer); }
    mbar_wait(mb_sf, par_sf); par_sf ^= 1u;   // sf halves exchanged

    // ---- P4: VpT for own 4 j (group-mapped: 64 active threads per group) ----
    {
        const int sub = (tid >> 6) & 1, bq = tid & 63;
        if (!sub){
            const int j = jbase + grp;
            float acc = 0.f;
            #pragma unroll
            for (int i = 0; i < 8; i++) acc += sf[i * 64 + bq] * scm[i * 8 + j];
            float part = __shfl_xor_sync(0xffffffffu, acc, 16);
            if (!(bq & 16)) VPB[grp * 32 + (((bq >> 5) << 4) | (bq & 15))] = pkh(acc, part);
        }
    }
    asm volatile("bar.sync %0, 128;" :: "r"(2 + grp) : "memory");

    // ---- P5: U1' own 4 j (512 threads; r = tid&127, jl = grp) ----
    {
        const int r = tid & 127;
        const uint4* A0 = (const uint4*)(VPB + grp * 32);
        __half2 a0 = ZH2, a1 = ZH2;
        #pragma unroll
        for (int c = 0; c < 8; c++) q_fma(a0, a1, W1H[c * 128 + r], A0[c]);
        float v0 = ss1[r] * hsum2h(a0, a1);
        float p0 = __shfl_xor_sync(0xffffffffu, v0, 16);
        if (!(r & 16)) D1B[grp * 64 + (((r >> 5) << 4) | (r & 15))] = pkh(v0, p0);
    }
    asm volatile("bar.sync %0, 128;" :: "r"(2 + grp) : "memory");

    // ---- P6: U2' own 4 j (512 threads; k = tid&127, jl = grp) ----
    {
        const int k = tid & 127;
        const uint4* A0 = (const uint4*)(D1B + grp * 64);
        __half2 a0 = ZH2, a1 = ZH2, a2 = ZH2, a3 = ZH2;
        #pragma unroll 4
        for (int c = 0; c < 16; c += 2){
            q_fma(a0, a1, W2H[c * 128 + k], A0[c]);
            q_fma(a2, a3, W2H[(c + 1) * 128 + k], A0[c + 1]);
        }
        float v0 = ss2[k] * (hsum2h(a0, a1) + hsum2h(a2, a3));
        float p0 = __shfl_xor_sync(0xffffffffu, v0, 16);
        if (!(k & 16)) EFB[grp * 64 + (((k >> 5) << 4) | (k & 15))] = pkh(v0, p0);
    }
    asm volatile("bar.sync %0, 128;" :: "r"(2 + grp) : "memory");

    // ---- P7: diag + folded g-term, own 256 rows (reads EFB of own group) ----
    {
        const int rowl = tid >> 1, kh = tid & 1, row = qbase + rowl;
        const int jl = rowl >> 6;   // == grp
        const uint4* A = (const uint4*)(EFB + jl * 64) + kh * 8;
        __half2 a0 = ZH2, a1 = ZH2, a2 = ZH2, a3 = ZH2;
        #pragma unroll
        for (int i = 0; i < 8; i += 2){
            q_fma(a0, a1, w3r[i], A[i]);
            q_fma(a2, a3, w3r[i + 1], A[i + 1]);
        }
        float part = hsum2h(a0, a1) + hsum2h(a2, a3);
        float other = __shfl_xor_sync(0xffffffffu, part, 1);
        if (!kh){
            float f = sf[row];
            float val = (1.0f - f * f) * (part + other) + gvec[jbase + jl] * f;
            sp[row] = val;
            st_peer_f32(sp_u32 + row * 4, peer, val);
        }
    }
    __syncwarp();
    if ((tid & 31) == 0){ mbar_arrive_local(mb_sp); mbar_arrive_peer(mb_sp, peer); }
    mbar_wait(mb_sp, par_sp); par_sp ^= 1u;   // sp halves exchanged

    // ---- P8: combine + Heun update + pack (64 threads; duplicated) ----
    if (tid < 64){
        float acc = 0.f;
        #pragma unroll
        for (int j = 0; j < 8; j++) acc += sp[j * 64 + tid];
        if (PH == 1){
            sm[OFF_K1 + tid] = acc;
            float ym = sm[OFF_Y + tid] + dt * acc;
            sm[OFF_YMID + tid] = ym;
            float part = __shfl_xor_sync(0xffffffffu, ym, 16);
            if (!(tid & 16)) ((u32*)(sm + OFF_YMB))[((tid >> 5) << 4) | (tid & 15)] = pkh(ym, part);
        } else {
            float yn = sm[OFF_Y + tid] + 0.5f * dt * (sm[OFF_K1 + tid] + acc);
            sm[OFF_Y + tid] = yn;
            float part = __shfl_xor_sync(0xffffffffu, yn, 16);
            if (!(tid & 16)) ((u32*)(sm + OFF_YB))[((tid >> 5) << 4) | (tid & 15)] = pkh(yn, part);
        }
    }
    __syncthreads();
}

__global__ void __launch_bounds__(NTH, 1) __cluster_dims__(2, 1, 1) ncde_kernel(
    const float* __restrict__ cv,
    const float* __restrict__ Wi1, const float* __restrict__ bi1,
    const float* __restrict__ Wi2, const float* __restrict__ bi2,
    const float* __restrict__ W1, const float* __restrict__ b1,
    const float* __restrict__ W2, const float* __restrict__ b2,
    const float* __restrict__ W3, const float* __restrict__ b3,
    const float* __restrict__ Wr, const float* __restrict__ br,
    const float* __restrict__ shiftp,
    float* __restrict__ out)
{
    const int tid = threadIdx.x;
    const int b = blockIdx.x >> 1;           // batch
    const u32 rank = my_cluster_rank();      // 0 or 1
    const u32 peer = rank ^ 1u;
    const int qbase = (int)rank * 256;
    const int jbase = (int)rank * 4;

    u32 smu;
    asm("{ .reg .u64 t; cvta.to.shared.u64 t, %1; cvt.u32.u64 %0, t; }"
        : "=r"(smu) : "l"(sm));
    const u32 mb_sf = smu + OFF_MB * 4;
    const u32 mb_sp = mb_sf + 8;
    u32 par_sf = 0, par_sp = 0;

    const float dt = (float)WINW / (float)(LD - 1);
    const float inv_dt = 1.0f / dt;

    float* sG = sm + OFF_G;
    float* sInc = sm + OFF_PART;

    // ---- W3 half-row -> registers: row = qbase + (tid>>1), chunks (tid&1)*8.. ----
    uint4 w3r[8];
    {
        const int row = qbase + (tid >> 1), kh = tid & 1;
        const float* rw = W3 + row * 128;
        #pragma unroll
        for (int i = 0; i < 8; i++){
            int c = kh * 8 + i;
            int base = (c >> 2) * 32 + (c & 3) * 4;
            w3r[i].x = pkh(rw[base + 0], rw[base + 16]);
            w3r[i].y = pkh(rw[base + 1], rw[base + 17]);
            w3r[i].z = pkh(rw[base + 2], rw[base + 18]);
            w3r[i].w = pkh(rw[base + 3], rw[base + 19]);
        }
    }

    // ---- init: pack W1/W2 fp16 pairs (k, k+16) into smem ----
    {
        u32* W1Hu = (u32*)(sm + OFF_W1H);
        for (int idx = tid; idx < 8 * 128; idx += NTH){
            int c = idx >> 7, r = idx & 127;
            int base = (c >> 2) * 32 + (c & 3) * 4;
            u32* dst = W1Hu + idx * 4;
            #pragma unroll
            for (int i = 0; i < 4; i++){
                int klo = base + i;
                dst[i] = pkh(W1[r * 64 + klo], W1[r * 64 + klo + 16]);
            }
        }
        u32* W2Hu = (u32*)(sm + OFF_W2H);
        for (int idx = tid; idx < 16 * 128; idx += NTH){
            int c = idx >> 7, k = idx & 127;
            int base = (c >> 2) * 32 + (c & 3) * 4;
            u32* dst = W2Hu + idx * 4;
            #pragma unroll
            for (int i = 0; i < 4; i++){
                int klo = base + i;
                dst[i] = pkh(W2[k * 128 + klo], W2[k * 128 + klo + 16]);
            }
        }
    }
    const float* cvb = cv + (size_t)b * LD * DD;
    for (int idx = tid; idx < 512 * 8; idx += NTH){
        sInc[idx] = cvb[idx + 8] - cvb[idx];
    }
    if (tid < 128) sm[OFF_B1 + tid] = b1[tid];
    else if (tid < 256) sm[OFF_B2 + tid - 128] = b2[tid - 128];
    else if (tid < 260) sm[OFF_BR + tid - 256] = br[tid - 256];
    else if (tid == 260) sm[OFF_SHIFT] = *shiftp;
    for (int idx = tid; idx < 512; idx += NTH) sm[OFF_B3 + idx] = b3[idx];
    for (int idx = tid; idx < 256; idx += NTH) sm[OFF_WR + idx] = Wr[idx];
    if (tid == 0){
        asm volatile("mbarrier.init.shared.b64 [%0], %1;" :: "r"(mb_sf), "r"(32u) : "memory");
        asm volatile("mbarrier.init.shared.b64 [%0], %1;" :: "r"(mb_sp), "r"(32u) : "memory");
        asm volatile("fence.mbarrier_init.release.cluster;" ::: "memory");
    }
    __syncthreads();

    // ---- window log-signatures (pre-divided by dt) + y0 (duplicated per CTA) ----
    for (int idx = tid; idx < NW * NPAIR; idx += NTH){
        int w = idx / NPAIR, p = idx % NPAIR;
        int i = PI_[p], j = PJ_[p];
        float acc = 0.f, pi = 0.f, pj = 0.f;
        const float* base = sInc + w * 16 * 8;
        #pragma unroll
        for (int s = 0; s < 16; s++){
            float ii = base[s * 8 + i], jj = base[s * 8 + j];
            acc += pi * jj - pj * ii;
            pi += ii; pj += jj;
        }
        sG[w * 36 + 8 + p] = 0.5f * acc * inv_dt;
    }
    for (int idx = tid; idx < NW * 8; idx += NTH){
        int w = idx >> 3, d2 = idx & 7;
        sG[w * 36 + d2] = (cvb[(16 * w + 16) * 8 + d2] - cvb[16 * w * 8 + d2]) * inv_dt;
    }
    if (tid < 64){
        float acc = bi1[tid];
        #pragma unroll
        for (int d2 = 0; d2 < 8; d2++) acc += Wi1[tid * 8 + d2] * cvb[d2];
        float dd; sm[OFF_SP + tid] = lipswish(acc, &dd);   // temp
    }
    __syncthreads();
    if (tid < 64){
        float acc = bi2[tid];
        #pragma unroll 8
        for (int h = 0; h < 64; h++) acc += Wi2[tid * 64 + h] * sm[OFF_SP + h];
        sm[OFF_Y + tid] = acc;
        float part = __shfl_xor_sync(0xffffffffu, acc, 16);
        if (!(tid & 16)) ((u32*)(sm + OFF_YB))[((tid >> 5) << 4) | (tid & 15)] = pkh(acc, part);
    }
    __syncthreads();
    CLUSTER_SYNC();   // publish mbarrier init before any remote arrive

    // ---- main Heun loop ----
    for (int n = 0; n < NW; n++){
        const float* gvec = sG + n * 36;
        // head folded into P1/P2 epoch (spare threads; scm consumed at P4)
        if (tid >= 256 && tid < 320){
            int t = tid - 256;
            int i = t >> 3, j = t & 7;
            float v = 0.0f;
            if (i < j) v = gvec[8 + pidx(i, j)];
            else if (i > j) v = -gvec[8 + pidx(j, i)];
            sm[OFF_CM + t] = v;
        } else if (rank == 0 && tid >= 320 && tid < 324){
            int o = tid - 320;
            float acc = sm[OFF_BR + o] + sm[OFF_SHIFT];
            #pragma unroll 8
            for (int a = 0; a < 64; a++) acc += sm[OFF_WR + o * 64 + a] * sm[OFF_Y + a];
            out[b * (NW + 1) * OUTD + n * OUTD + o] = acc;
        }

        vf_apply<1>(tid, w3r, peer, qbase, jbase, smu, mb_sf, mb_sp, par_sf, par_sp, gvec, dt);
        vf_apply<2>(tid, w3r, peer, qbase, jbase, smu, mb_sf, mb_sp, par_sf, par_sp, gvec, dt);
    }

    // final readout (index NW) — rank 0 only
    if (rank == 0 && tid < 4){
        float acc = sm[OFF_BR + tid] + sm[OFF_SHIFT];
        #pragma unroll 8
        for (int a = 0; a < 64; a++) acc += sm[OFF_WR + tid * 64 + a] * sm[OFF_Y + a];
        out[b * (NW + 1) * OUTD + NW * OUTD + tid] = acc;
    }
    CLUSTER_SYNC();   // keep peer smem alive until all cross-traffic done
}

extern "C" void kernel_launch(void* const* d_in, const int* in_sizes, int n_in,
                              void* d_out, int out_size) {
    (void)in_sizes; (void)n_in; (void)out_size;
    const size_t smem = SMEM_FLOATS * sizeof(float);  // 85,808 B
    cudaFuncSetAttribute(ncde_kernel, cudaFuncAttributeMaxDynamicSharedMemorySize, (int)smem);
    ncde_kernel<<<BD * 2, NTH, smem>>>(
        (const float*)d_in[0],
        (const float*)d_in[1], (const float*)d_in[2],
        (const float*)d_in[3], (const float*)d_in[4],
        (const float*)d_in[5], (const float*)d_in[6],
        (const float*)d_in[7], (const float*)d_in[8],
        (const float*)d_in[9], (const float*)d_in[10],
        (const float*)d_in[11], (const float*)d_in[12],
        (const float*)d_in[13],
        (float*)d_out);
}

// round 16
// speedup vs baseline: 1.1056x; 1.1056x over previous
#include <cuda_runtime.h>
#include <cuda_fp16.h>

typedef unsigned long long u64;
typedef unsigned int u32;

#define BD   32
#define LD   513
#define DD   8
#define HD   64
#define WINW 16
#define NW   32
#define OUTD 4
#define NPAIR 28
#define NTH  512

// ---- smem layout (float offsets; 16B-aligned). W3 half in regs (32/thread). ----
#define OFF_W1H  0        // uint4[8*128] : W1H[c*128+r], K=64
#define OFF_W2H  4096     // uint4[16*128]: W2H[c*128+k], K=128
#define OFF_G    12288    // 1152
#define OFF_Y    13440    // 64
#define OFF_YMID 13504    // 64
#define OFF_K1   13568    // 64
#define OFF_CM   13632    // 64
#define OFF_S1   13696    // 128
#define OFF_S2   13824    // 128
#define OFF_F    13952    // 512 (full sf; halves exchanged via DSMEM)
#define OFF_SP   14464    // 1024 = 2 slots x 512 (double-buffered by Heun phase)
#define OFF_YB   15488    // 32 u32
#define OFF_YMB  15520    // 32 u32
#define OFF_H1B  15552    // 64 u32
#define OFF_H2B  15616    // 64 u32
#define OFF_VPB  15680    // 128 u32 (4 local j x 32)
#define OFF_D1B  15808    // 256 u32 (4 local j x 64)
#define OFF_EFB  16064    // 256 u32 (4 local j x 64)
#define OFF_B1   16320    // 128
#define OFF_B2   16448    // 128
#define OFF_B3   16576    // 512
#define OFF_WR   17088    // 256
#define OFF_BR   17344    // 4
#define OFF_SHIFT 17348
#define OFF_PART 17352    // 4096 staging (init only)
#define SMEM_FLOATS 21448 // 85,792 B

__device__ const signed char PI_[NPAIR] = {0,0,0,0,0,0,0, 1,1,1,1,1,1, 2,2,2,2,2, 3,3,3,3, 4,4,4, 5,5, 6};
__device__ const signed char PJ_[NPAIR] = {1,2,3,4,5,6,7, 2,3,4,5,6,7, 3,4,5,6,7, 4,5,6,7, 5,6,7, 6,7, 7};

// ---------- fast math ----------
__device__ __forceinline__ float ex2f(float x){ float y; asm("ex2.approx.f32 %0, %1;" : "=f"(y) : "f"(x)); return y; }
__device__ __forceinline__ float rcpf(float x){ float y; asm("rcp.approx.f32 %0, %1;" : "=f"(y) : "f"(x)); return y; }
__device__ __forceinline__ float sigf(float x){ return rcpf(1.0f + ex2f(-1.4426950408889634f * x)); }
__device__ __forceinline__ float tanh_fast(float x){
    float t = ex2f(2.8853900817779268f * x);
    return 1.0f - 2.0f * rcpf(t + 1.0f);
}
__device__ __forceinline__ float lipswish(float x, float* dout){
    float s = sigf(x);
    *dout = 0.909f * s * fmaf(x, 1.0f - s, 1.0f);
    return 0.909f * x * s;
}

// ---------- fp16 helpers ----------
__device__ __forceinline__ __half2 u2h(u32 u){ return *reinterpret_cast<__half2*>(&u); }
__device__ __forceinline__ u32 h2u(__half2 h){ return *reinterpret_cast<u32*>(&h); }
__device__ __forceinline__ u32 pkh(float lo, float hi){ return h2u(__floats2half2_rn(lo, hi)); }
__device__ __forceinline__ float hsum2h(__half2 a, __half2 b){
    float2 fa = __half22float2(a), fb = __half22float2(b);
    return (fa.x + fa.y) + (fb.x + fb.y);
}
__device__ __forceinline__ void q_fma(__half2& a0, __half2& a1, uint4 w, uint4 x){
    a0 = __hfma2(u2h(w.x), u2h(x.x), a0);
    a1 = __hfma2(u2h(w.y), u2h(x.y), a1);
    a0 = __hfma2(u2h(w.z), u2h(x.z), a0);
    a1 = __hfma2(u2h(w.w), u2h(x.w), a1);
}

__device__ __forceinline__ int pidx(int i, int j) { return (i * (13 - i)) / 2 + j - 1; }

// ---------- cluster helpers ----------
__device__ __forceinline__ u32 my_cluster_rank(){
    u32 r; asm("mov.u32 %0, %%cluster_ctarank;" : "=r"(r)); return r;
}
__device__ __forceinline__ void st_peer_f32(u32 laddr, u32 peer, float v){
    u32 raddr;
    asm volatile("mapa.shared::cluster.u32 %0, %1, %2;" : "=r"(raddr) : "r"(laddr), "r"(peer));
    asm volatile("st.shared::cluster.f32 [%0], %1;" :: "r"(raddr), "f"(v) : "memory");
}
#define CLUSTER_SYNC() do { \
    asm volatile("barrier.cluster.arrive.aligned;" ::: "memory"); \
    asm volatile("barrier.cluster.wait.aligned;" ::: "memory"); \
} while(0)

extern __shared__ float sm[];

#define ZH2 (__half2(__float2half_rn(0.f), __float2half_rn(0.f)))

// PH=1: acts=yb, writes sk1/symid(+pack). PH=2: acts=ymb, updates sy(+pack).
// Rank q owns rows qbase..qbase+255 (P3/P7) and j = jbase..jbase+3 (P4/P5/P6).
template<int PH>
__device__ __forceinline__ void vf_apply(int tid, const uint4* __restrict__ w3r,
                                         u32 peer, int qbase, int jbase, u32 smu,
                                         const float* __restrict__ gvec, float dt)
{
    const uint4* W1H = (const uint4*)(sm + OFF_W1H);
    const uint4* W2H = (const uint4*)(sm + OFF_W2H);
    float* ss1 = sm + OFF_S1;  float* ss2 = sm + OFF_S2;
    float* sf  = sm + OFF_F;
    float* sp  = sm + OFF_SP + (PH - 1) * 512;   // double-buffered by phase
    const u32 sp_u32 = smu + (OFF_SP + (PH - 1) * 512) * 4;
    const u32 sf_u32 = smu + OFF_F * 4;
    u32* H1B = (u32*)(sm + OFF_H1B);
    u32* H2B = (u32*)(sm + OFF_H2B);
    u32* VPB = (u32*)(sm + OFF_VPB);
    u32* D1B = (u32*)(sm + OFF_D1B);
    u32* EFB = (u32*)(sm + OFF_EFB);
    const float* scm = sm + OFF_CM;
    const int grp = tid >> 7;   // 4-warp group id (named barriers 2..5)

    // ---- P1 + P2 (tid<128; duplicated in both CTAs; named barrier between) ----
    if (tid < 128) {
        {   // P1: L1 forward
            const int r = tid;
            const uint4* A = (const uint4*)(sm + (PH == 1 ? OFF_YB : OFF_YMB));
            __half2 a0 = ZH2, a1 = ZH2, a2 = ZH2, a3 = ZH2;
            #pragma unroll
            for (int c = 0; c < 8; c += 2){
                q_fma(a0, a1, W1H[c * 128 + r], A[c]);
                q_fma(a2, a3, W1H[(c + 1) * 128 + r], A[c + 1]);
            }
            float pre = sm[OFF_B1 + r] + hsum2h(a0, a1) + hsum2h(a2, a3);
            float d; float hv = lipswish(pre, &d); ss1[r] = d;
            float part = __shfl_xor_sync(0xffffffffu, hv, 16);
            if (!(r & 16)) H1B[((r >> 5) << 4) | (r & 15)] = pkh(hv, part);
        }
        asm volatile("bar.sync 1, 128;" ::: "memory");
        {   // P2: L2 forward
            const int k = tid;
            const uint4* A = (const uint4*)H1B;
            __half2 a0 = ZH2, a1 = ZH2, a2 = ZH2, a3 = ZH2;
            #pragma unroll 4
            for (int c = 0; c < 16; c += 2){
                q_fma(a0, a1, W2H[c * 128 + k], A[c]);
                q_fma(a2, a3, W2H[(c + 1) * 128 + k], A[c + 1]);
            }
            float pre = sm[OFF_B2 + k] + hsum2h(a0, a1) + hsum2h(a2, a3);
            float d; float hv = lipswish(pre, &d); ss2[k] = d;
            float part = __shfl_xor_sync(0xffffffffu, hv, 16);
            if (!(k & 16)) H2B[((k >> 5) << 4) | (k & 15)] = pkh(hv, part);
        }
    }
    __syncthreads();

    // ---- P3: L3 forward, own 256 rows, 2 threads/row (K halves) ----
    {
        const int rowl = tid >> 1, kh = tid & 1, row = qbase + rowl;
        const uint4* A = (const uint4*)H2B + kh * 8;
        __half2 a0 = ZH2, a1 = ZH2, a2 = ZH2, a3 = ZH2;
        #pragma unroll
        for (int i = 0; i < 8; i += 2){
            q_fma(a0, a1, w3r[i], A[i]);
            q_fma(a2, a3, w3r[i + 1], A[i + 1]);
        }
        float part = hsum2h(a0, a1) + hsum2h(a2, a3);
        float other = __shfl_xor_sync(0xffffffffu, part, 1);
        if (!kh){
            float f = tanh_fast(sm[OFF_B3 + row] + part + other);
            sf[row] = f;
            st_peer_f32(sf_u32 + row * 4, peer, f);
        }
    }
    CLUSTER_SYNC();   // sf halves exchanged (CTA-wide sync too)

    // ---- P4: VpT for own 4 j, group-local (64 active threads per group) ----
    {
        const int sub = (tid >> 6) & 1, bq = tid & 63;
        if (!sub){
            const int j = jbase + grp;
            float acc = 0.f;
            #pragma unroll
            for (int i = 0; i < 8; i++) acc += sf[i * 64 + bq] * scm[i * 8 + j];
            float part = __shfl_xor_sync(0xffffffffu, acc, 16);
            if (!(bq & 16)) VPB[grp * 32 + (((bq >> 5) << 4) | (bq & 15))] = pkh(acc, part);
        }
    }
    asm volatile("bar.sync %0, 128;" :: "r"(2 + grp) : "memory");

    // ---- P5: U1' own j = grp (group-local; r = tid&127) ----
    {
        const int r = tid & 127;
        const uint4* A0 = (const uint4*)(VPB + grp * 32);
        __half2 a0 = ZH2, a1 = ZH2;
        #pragma unroll
        for (int c = 0; c < 8; c++) q_fma(a0, a1, W1H[c * 128 + r], A0[c]);
        float v0 = ss1[r] * hsum2h(a0, a1);
        float p0 = __shfl_xor_sync(0xffffffffu, v0, 16);
        if (!(r & 16)) D1B[grp * 64 + (((r >> 5) << 4) | (r & 15))] = pkh(v0, p0);
    }
    asm volatile("bar.sync %0, 128;" :: "r"(2 + grp) : "memory");

    // ---- P6: U2' own j = grp (group-local; k = tid&127) ----
    {
        const int k = tid & 127;
        const uint4* A0 = (const uint4*)(D1B + grp * 64);
        __half2 a0 = ZH2, a1 = ZH2, a2 = ZH2, a3 = ZH2;
        #pragma unroll 4
        for (int c = 0; c < 16; c += 2){
            q_fma(a0, a1, W2H[c * 128 + k], A0[c]);
            q_fma(a2, a3, W2H[(c + 1) * 128 + k], A0[c + 1]);
        }
        float v0 = ss2[k] * (hsum2h(a0, a1) + hsum2h(a2, a3));
        float p0 = __shfl_xor_sync(0xffffffffu, v0, 16);
        if (!(k & 16)) EFB[grp * 64 + (((k >> 5) << 4) | (k & 15))] = pkh(v0, p0);
    }
    asm volatile("bar.sync %0, 128;" :: "r"(2 + grp) : "memory");

    // ---- P7: diag + folded g-term, own 256 rows (EFB of own group: tid>>7 == grp) ----
    {
        const int rowl = tid >> 1, kh = tid & 1, row = qbase + rowl;
        const int jl = rowl >> 6;   // == grp
        const uint4* A = (const uint4*)(EFB + jl * 64) + kh * 8;
        __half2 a0 = ZH2, a1 = ZH2, a2 = ZH2, a3 = ZH2;
        #pragma unroll
        for (int i = 0; i < 8; i += 2){
            q_fma(a0, a1, w3r[i], A[i]);
            q_fma(a2, a3, w3r[i + 1], A[i + 1]);
        }
        float part = hsum2h(a0, a1) + hsum2h(a2, a3);
        float other = __shfl_xor_sync(0xffffffffu, part, 1);
        if (!kh){
            float f = sf[row];
            float val = (1.0f - f * f) * (part + other) + gvec[jbase + jl] * f;
            sp[row] = val;
            st_peer_f32(sp_u32 + row * 4, peer, val);
        }
    }
    CLUSTER_SYNC();   // sp halves exchanged

    // ---- P8: combine + Heun update + pack (64 threads; duplicated) ----
    if (tid < 64){
        float acc = 0.f;
        #pragma unroll
        for (int j = 0; j < 8; j++) acc += sp[j * 64 + tid];
        if (PH == 1){
            sm[OFF_K1 + tid] = acc;
            float ym = sm[OFF_Y + tid] + dt * acc;
            sm[OFF_YMID + tid] = ym;
            float part = __shfl_xor_sync(0xffffffffu, ym, 16);
            if (!(tid & 16)) ((u32*)(sm + OFF_YMB))[((tid >> 5) << 4) | (tid & 15)] = pkh(ym, part);
        } else {
            float yn = sm[OFF_Y + tid] + 0.5f * dt * (sm[OFF_K1 + tid] + acc);
            sm[OFF_Y + tid] = yn;
            float part = __shfl_xor_sync(0xffffffffu, yn, 16);
            if (!(tid & 16)) ((u32*)(sm + OFF_YB))[((tid >> 5) << 4) | (tid & 15)] = pkh(yn, part);
        }
    }
    __syncthreads();
}

__global__ void __launch_bounds__(NTH, 1) __cluster_dims__(2, 1, 1) ncde_kernel(
    const float* __restrict__ cv,
    const float* __restrict__ Wi1, const float* __restrict__ bi1,
    const float* __restrict__ Wi2, const float* __restrict__ bi2,
    const float* __restrict__ W1, const float* __restrict__ b1,
    const float* __restrict__ W2, const float* __restrict__ b2,
    const float* __restrict__ W3, const float* __restrict__ b3,
    const float* __restrict__ Wr, const float* __restrict__ br,
    const float* __restrict__ shiftp,
    float* __restrict__ out)
{
    const int tid = threadIdx.x;
    const int b = blockIdx.x >> 1;           // batch
    const u32 rank = my_cluster_rank();      // 0 or 1
    const u32 peer = rank ^ 1u;
    const int qbase = (int)rank * 256;
    const int jbase = (int)rank * 4;

    u32 smu;
    asm("{ .reg .u64 t; cvta.to.shared.u64 t, %1; cvt.u32.u64 %0, t; }"
        : "=r"(smu) : "l"(sm));

    const float dt = (float)WINW / (float)(LD - 1);
    const float inv_dt = 1.0f / dt;

    float* sG = sm + OFF_G;
    float* sInc = sm + OFF_PART;

    // ---- W3 half-row -> registers: row = qbase + (tid>>1), chunks (tid&1)*8.. ----
    uint4 w3r[8];
    {
        const int row = qbase + (tid >> 1), kh = tid & 1;
        const float* rw = W3 + row * 128;
        #pragma unroll
        for (int i = 0; i < 8; i++){
            int c = kh * 8 + i;
            int base = (c >> 2) * 32 + (c & 3) * 4;
            w3r[i].x = pkh(rw[base + 0], rw[base + 16]);
            w3r[i].y = pkh(rw[base + 1], rw[base + 17]);
            w3r[i].z = pkh(rw[base + 2], rw[base + 18]);
            w3r[i].w = pkh(rw[base + 3], rw[base + 19]);
        }
    }

    // ---- init: pack W1/W2 fp16 pairs (k, k+16) into smem ----
    {
        u32* W1Hu = (u32*)(sm + OFF_W1H);
        for (int idx = tid; idx < 8 * 128; idx += NTH){
            int c = idx >> 7, r = idx & 127;
            int base = (c >> 2) * 32 + (c & 3) * 4;
            u32* dst = W1Hu + idx * 4;
            #pragma unroll
            for (int i = 0; i < 4; i++){
                int klo = base + i;
                dst[i] = pkh(W1[r * 64 + klo], W1[r * 64 + klo + 16]);
            }
        }
        u32* W2Hu = (u32*)(sm + OFF_W2H);
        for (int idx = tid; idx < 16 * 128; idx += NTH){
            int c = idx >> 7, k = idx & 127;
            int base = (c >> 2) * 32 + (c & 3) * 4;
            u32* dst = W2Hu + idx * 4;
            #pragma unroll
            for (int i = 0; i < 4; i++){
                int klo = base + i;
                dst[i] = pkh(W2[k * 128 + klo], W2[k * 128 + klo + 16]);
            }
        }
    }
    const float* cvb = cv + (size_t)b * LD * DD;
    for (int idx = tid; idx < 512 * 8; idx += NTH){
        sInc[idx] = cvb[idx + 8] - cvb[idx];
    }
    if (tid < 128) sm[OFF_B1 + tid] = b1[tid];
    else if (tid < 256) sm[OFF_B2 + tid - 128] = b2[tid - 128];
    else if (tid < 260) sm[OFF_BR + tid - 256] = br[tid - 256];
    else if (tid == 260) sm[OFF_SHIFT] = *shiftp;
    for (int idx = tid; idx < 512; idx += NTH) sm[OFF_B3 + idx] = b3[idx];
    for (int idx = tid; idx < 256; idx += NTH) sm[OFF_WR + idx] = Wr[idx];
    __syncthreads();

    // ---- window log-signatures (pre-divided by dt) + y0 (duplicated per CTA) ----
    for (int idx = tid; idx < NW * NPAIR; idx += NTH){
        int w = idx / NPAIR, p = idx % NPAIR;
        int i = PI_[p], j = PJ_[p];
        float acc = 0.f, pi = 0.f, pj = 0.f;
        const float* base = sInc + w * 16 * 8;
        #pragma unroll
        for (int s = 0; s < 16; s++){
            float ii = base[s * 8 + i], jj = base[s * 8 + j];
            acc += pi * jj - pj * ii;
            pi += ii; pj += jj;
        }
        sG[w * 36 + 8 + p] = 0.5f * acc * inv_dt;
    }
    for (int idx = tid; idx < NW * 8; idx += NTH){
        int w = idx >> 3, d2 = idx & 7;
        sG[w * 36 + d2] = (cvb[(16 * w + 16) * 8 + d2] - cvb[16 * w * 8 + d2]) * inv_dt;
    }
    if (tid < 64){
        float acc = bi1[tid];
        #pragma unroll
        for (int d2 = 0; d2 < 8; d2++) acc += Wi1[tid * 8 + d2] * cvb[d2];
        float dd; sm[OFF_SP + tid] = lipswish(acc, &dd);   // temp
    }
    __syncthreads();
    if (tid < 64){
        float acc = bi2[tid];
        #pragma unroll 8
        for (int h = 0; h < 64; h++) acc += Wi2[tid * 64 + h] * sm[OFF_SP + h];
        sm[OFF_Y + tid] = acc;
        float part = __shfl_xor_sync(0xffffffffu, acc, 16);
        if (!(tid & 16)) ((u32*)(sm + OFF_YB))[((tid >> 5) << 4) | (tid & 15)] = pkh(acc, part);
    }
    __syncthreads();

    // ---- main Heun loop ----
    for (int n = 0; n < NW; n++){
        const float* gvec = sG + n * 36;
        // head folded into P1/P2 epoch (spare threads; scm consumed at P4)
        if (tid >= 256 && tid < 320){
            int t = tid - 256;
            int i = t >> 3, j = t & 7;
            float v = 0.0f;
            if (i < j) v = gvec[8 + pidx(i, j)];
            else if (i > j) v = -gvec[8 + pidx(j, i)];
            sm[OFF_CM + t] = v;
        } else if (rank == 0 && tid >= 320 && tid < 324){
            int o = tid - 320;
            float acc = sm[OFF_BR + o] + sm[OFF_SHIFT];
            #pragma unroll 8
            for (int a = 0; a < 64; a++) acc += sm[OFF_WR + o * 64 + a] * sm[OFF_Y + a];
            out[b * (NW + 1) * OUTD + n * OUTD + o] = acc;
        }

        vf_apply<1>(tid, w3r, peer, qbase, jbase, smu, gvec, dt);
        vf_apply<2>(tid, w3r, peer, qbase, jbase, smu, gvec, dt);
    }

    // final readout (index NW) — rank 0 only
    if (rank == 0 && tid < 4){
        float acc = sm[OFF_BR + tid] + sm[OFF_SHIFT];
        #pragma unroll 8
        for (int a = 0; a < 64; a++) acc += sm[OFF_WR + tid * 64 + a] * sm[OFF_Y + a];
        out[b * (NW + 1) * OUTD + NW * OUTD + tid] = acc;
    }
    CLUSTER_SYNC();   // keep peer smem alive until all cross-traffic done
}

extern "C" void kernel_launch(void* const* d_in, const int* in_sizes, int n_in,
                              void* d_out, int out_size) {
    (void)in_sizes; (void)n_in; (void)out_size;
    const size_t smem = SMEM_FLOATS * sizeof(float);  // 85,792 B
    cudaFuncSetAttribute(ncde_kernel, cudaFuncAttributeMaxDynamicSharedMemorySize, (int)smem);
    ncde_kernel<<<BD * 2, NTH, smem>>>(
        (const float*)d_in[0],
        (const float*)d_in[1], (const float*)d_in[2],
        (const float*)d_in[3], (const float*)d_in[4],
        (const float*)d_in[5], (const float*)d_in[6],
        (const float*)d_in[7], (const float*)d_in[8],
        (const float*)d_in[9], (const float*)d_in[10],
        (const float*)d_in[11], (const float*)d_in[12],
        (const float*)d_in[13],
        (float*)d_out);
}